// round 5
// baseline (speedup 1.0000x reference)
#include <cuda_runtime.h>

// Problem constants
#define PP 12
#define BB 4
#define KSTEP 12
#define TE_DEPTH 168
#define NUM_CELLS 1024   // 32*32
#define PQ 24            // P + Q

// Output layout (tuple flattened, row-major each):
//  Y       (B,1,H,W,1)       4096   @ 0
//  x       (B,P,H,W,1)      49152   @ 4096
//  trans   (B,P,H,W,8,1)   393216   @ 53248
//  restart (B,P,H,W,1)      49152   @ 446464
//  results (B,P,H,W,1,13)  638976   @ 495616
#define OFF_Y    0
#define OFF_X    4096
#define OFF_T    53248
#define OFF_R    446464
#define OFF_RES  495616

// Dynamic smem layout (floats):
//  tp    @ 0      : 8 planes of 34x34 (9248)
//  xs    @ 9248   : 2 buffers of 34x34 (2312)
//  stage @ 11560  : 1024*13 results staging (13312)
#define TP_OFF    0
#define XS_OFF    9248
#define STG_OFF   11560
#define SMEM_FLOATS (STG_OFF + 13312)   // 24872 floats = 99488 B

__global__ __launch_bounds__(1024, 1) void rwr_kernel(
    const float* __restrict__ X,
    const int*   __restrict__ TE,
    const float* __restrict__ Wt,   // (1192, 8)
    const float* __restrict__ Wr,   // (1192, 1)
    const float* __restrict__ Wb,   // (1192, 1)
    float*       __restrict__ out)
{
    extern __shared__ __align__(16) float sm[];
    float* tp    = sm + TP_OFF;     // tp[d][r][c] = tp[d*1156 + r*34 + c]
    float* xs    = sm + XS_OFF;     // xs[buf][r][c] = xs[buf*1156 + r*34 + c]
    float* stage = sm + STG_OFF;

    const int bp   = blockIdx.x;        // 0..47
    const int b    = bp / PP;
    const int p    = bp % PP;
    const int cell = threadIdx.x;       // 0..1023
    const int h    = cell >> 5;
    const int w    = cell & 31;

    // ---- prefetch all globals up front (MLP) ----
    const float x0 = X[bp * NUM_CELLS + cell];
    const int te_day  = TE[(b * PQ + p) * 2 + 0];
    const int te_hour = TE[(b * PQ + p) * 2 + 1];
    const int te = te_day * 24 + te_hour;            // < 168
    const int cr = TE_DEPTH + cell;

    const float4* wc4 = reinterpret_cast<const float4*>(Wt + (size_t)cr * 8);
    const float4 wc_lo = wc4[0];
    const float4 wc_hi = wc4[1];
    const float4* wt4 = reinterpret_cast<const float4*>(Wt + (size_t)te * 8);
    const float4 wt_lo = wt4[0];
    const float4 wt_hi = wt4[1];
    const float wr_te = Wr[te], wr_c = Wr[cr];
    const float wb_te = Wb[te], wb_c = Wb[cr];

    // ---- zero ONLY the borders: tp planes (8*132) + xs buffers (2*132) ----
    // Disjoint from the interior cells written below -> no barrier needed
    // between zeroing and interior fill (one barrier before reads suffices).
    #pragma unroll
    for (int i = cell; i < 1320; i += 1024) {
        const int plane = i / 132;       // 0..7 -> tp planes, 8..9 -> xs buffers
        const int j = i % 132;
        int rr, cc;
        if      (j <  34) { rr = 0;       cc = j; }
        else if (j <  68) { rr = 33;      cc = j - 34; }
        else if (j < 100) { rr = j - 67;  cc = 0;  }   // rows 1..32
        else              { rr = j - 99;  cc = 33; }   // rows 1..32
        float* base = (plane < 8) ? (tp + plane * 1156)
                                  : (xs + (plane - 8) * 1156);
        base[rr * 34 + cc] = 0.f;
    }

    // ---- softmax over 8 dirs (fast math; logits tiny, skip max-sub) ----
    float lg[8];
    lg[0] = wt_lo.x + wc_lo.x;  lg[1] = wt_lo.y + wc_lo.y;
    lg[2] = wt_lo.z + wc_lo.z;  lg[3] = wt_lo.w + wc_lo.w;
    lg[4] = wt_hi.x + wc_hi.x;  lg[5] = wt_hi.y + wc_hi.y;
    lg[6] = wt_hi.z + wc_hi.z;  lg[7] = wt_hi.w + wc_hi.w;
    float e[8], s = 0.f;
    #pragma unroll
    for (int d = 0; d < 8; d++) { e[d] = __expf(lg[d]); s += e[d]; }
    const float inv_s = __fdividef(1.0f, s);
    float tpv[8];
    #pragma unroll
    for (int d = 0; d < 8; d++) tpv[d] = e[d] * inv_s;

    // restart (sigmoid) and bias
    const float rz = wr_te + wr_c;
    const float restart = __fdividef(1.0f, 1.0f + __expf(-rz));
    const float one_m_r = 1.0f - restart;
    const float bias = (wb_te + wb_c) * x0;

    // ---- static outputs (fire-and-forget stores) ----
    {
        float4* t4 = reinterpret_cast<float4*>(out + OFF_T + (size_t)(bp * NUM_CELLS + cell) * 8);
        t4[0] = make_float4(tpv[0], tpv[1], tpv[2], tpv[3]);
        t4[1] = make_float4(tpv[4], tpv[5], tpv[6], tpv[7]);
    }
    out[OFF_R + bp * NUM_CELLS + cell] = restart;

    // fill tp interior (disjoint from border zeroes above)
    const int ctr = (h + 1) * 34 + (w + 1);
    #pragma unroll
    for (int d = 0; d < 8; d++) tp[d * 1156 + ctr] = tpv[d];
    __syncthreads();   // tp borders + interior ready

    // DIRS d: 0:(-1,-1) 1:(-1,0) 2:(-1,1) 3:(0,-1) 4:(0,1) 5:(1,-1) 6:(1,0) 7:(1,1)
    const int DOF[8] = {-35, -34, -33, -1, 1, 33, 34, 35};   // offsets in 34-wide rows

    // incoming weight from neighbor via channel d
    float w_in[8];
    #pragma unroll
    for (int d = 0; d < 8; d++)
        w_in[d] = tp[d * 1156 + ctr + DOF[d]];

    // ---- iterate; stage results to smem as we go ----
    float x = x0;
    stage[cell * 13 + 0] = x0;

    #pragma unroll
    for (int k = 0; k < KSTEP; k++) {
        float* xb = xs + (k & 1) * 1156;
        xb[ctr] = x;
        __syncthreads();
        float a0 = xb[ctr - 35] * w_in[0];
        float a1 = xb[ctr - 34] * w_in[1];
        float a2 = xb[ctr - 33] * w_in[2];
        float a3 = xb[ctr -  1] * w_in[3];
        a0 = fmaf(xb[ctr +  1], w_in[4], a0);
        a1 = fmaf(xb[ctr + 33], w_in[5], a1);
        a2 = fmaf(xb[ctr + 34], w_in[6], a2);
        a3 = fmaf(xb[ctr + 35], w_in[7], a3);
        const float xt = (a0 + a1) + (a2 + a3);
        x = fmaf(one_m_r, xt, fmaf(restart, x, bias));
        stage[cell * 13 + (k + 1)] = x;     // odd stride -> conflict-free
    }

    // final state x (coalesced) + Y
    out[OFF_X + bp * NUM_CELLS + cell] = x;
    if (p == PP - 1)
        out[OFF_Y + b * NUM_CELLS + cell] = x;

    // ---- one barrier, then fully coalesced results dump (3328 float4) ----
    __syncthreads();
    const float4* s4 = reinterpret_cast<const float4*>(stage);
    float4* o4 = reinterpret_cast<float4*>(out + OFF_RES + (size_t)bp * (NUM_CELLS * 13));
    #pragma unroll
    for (int i = 0; i < 4; i++) {
        const int idx = cell + i * 1024;
        if (idx < 3328) o4[idx] = s4[idx];
    }
}

extern "C" void kernel_launch(void* const* d_in, const int* in_sizes, int n_in,
                              void* d_out, int out_size) {
    const float* X  = (const float*)d_in[0];
    const int*   TE = (const int*)d_in[1];
    const float* Wt = (const float*)d_in[2];
    const float* Wr = (const float*)d_in[3];
    const float* Wb = (const float*)d_in[4];
    float* out = (float*)d_out;
    const int smem_bytes = SMEM_FLOATS * 4;   // 99488 B
    cudaFuncSetAttribute(rwr_kernel, cudaFuncAttributeMaxDynamicSharedMemorySize, smem_bytes);
    rwr_kernel<<<BB * PP, 1024, smem_bytes>>>(X, TE, Wt, Wr, Wb, out);
}

// round 6
// speedup vs baseline: 1.0233x; 1.0233x over previous
#include <cuda_runtime.h>

// Problem constants
#define PP 12
#define BB 4
#define KSTEP 12
#define TE_DEPTH 168
#define NUM_CELLS 1024   // 32*32
#define PQ 24            // P + Q

// Output layout (tuple flattened, row-major each):
//  Y       (B,1,H,W,1)       4096   @ 0
//  x       (B,P,H,W,1)      49152   @ 4096
//  trans   (B,P,H,W,8,1)   393216   @ 53248
//  restart (B,P,H,W,1)      49152   @ 446464
//  results (B,P,H,W,1,13)  638976   @ 495616
#define OFF_Y    0
#define OFF_X    4096
#define OFF_T    53248
#define OFF_R    446464
#define OFF_RES  495616

// Dynamic smem layout (floats):
//  tp    @ 0      : 8 planes of 34x34 (9248), row stride 34
//  xs    @ 9248   : 2 buffers of 34 rows x 36 stride (2448) -- interior cols 2..33,
//                   so the (even) pair base is 8B-aligned for STS.64/LDS.64
//  stage @ 11696  : 1024*13 results staging (13312)
#define TP_OFF    0
#define XS_OFF    9248
#define XS_STRIDE 36
#define XS_SIZE   (34 * XS_STRIDE)      // 1224
#define STG_OFF   (XS_OFF + 2 * XS_SIZE)  // 11696
#define SMEM_FLOATS (STG_OFF + 13312)     // 25008 floats = 100032 B

__global__ __launch_bounds__(512, 1) void rwr_kernel(
    const float* __restrict__ X,
    const int*   __restrict__ TE,
    const float* __restrict__ Wt,   // (1192, 8)
    const float* __restrict__ Wr,   // (1192, 1)
    const float* __restrict__ Wb,   // (1192, 1)
    float*       __restrict__ out)
{
    extern __shared__ __align__(16) float sm[];
    float* tp    = sm + TP_OFF;
    float* xs    = sm + XS_OFF;
    float* stage = sm + STG_OFF;

    const int bp   = blockIdx.x;        // 0..47
    const int b    = bp / PP;
    const int p    = bp % PP;
    const int tid  = threadIdx.x;       // 0..511
    const int h    = tid >> 4;          // row 0..31
    const int wp   = (tid & 15) << 1;   // even col base 0..30
    const int cell0 = (h << 5) + wp;    // even

    // ---- prefetch all globals up front (MLP) ----
    const float2 xin = *reinterpret_cast<const float2*>(X + bp * NUM_CELLS + cell0);
    const int te_day  = TE[(b * PQ + p) * 2 + 0];
    const int te_hour = TE[(b * PQ + p) * 2 + 1];
    const int te = te_day * 24 + te_hour;            // < 168
    const int cr0 = TE_DEPTH + cell0;

    const float4* wc4a = reinterpret_cast<const float4*>(Wt + (size_t)cr0 * 8);
    const float4 wca_lo = wc4a[0], wca_hi = wc4a[1];
    const float4 wcb_lo = wc4a[2], wcb_hi = wc4a[3];     // next cell's row
    const float4* wt4 = reinterpret_cast<const float4*>(Wt + (size_t)te * 8);
    const float4 wt_lo = wt4[0], wt_hi = wt4[1];
    const float2 wrc = *reinterpret_cast<const float2*>(Wr + cr0);
    const float2 wbc = *reinterpret_cast<const float2*>(Wb + cr0);
    const float wr_te = Wr[te];
    const float wb_te = Wb[te];

    // ---- zero ONLY borders: tp planes (8*132) + xs buffers (2*132) ----
    // tp: rows 0,33 cols 0..33; cols 0,33 rows 1..32  (stride 34)
    // xs: rows 0,33 cols 1..34; cols 1,34 rows 1..32  (stride 36)
    #pragma unroll
    for (int i = tid; i < 1320; i += 512) {
        const int plane = i / 132;       // 0..7 tp, 8..9 xs
        const int j = i % 132;
        int rr, cc;
        if      (j <  34) { rr = 0;       cc = j; }
        else if (j <  68) { rr = 33;      cc = j - 34; }
        else if (j < 100) { rr = j - 67;  cc = 0;  }
        else              { rr = j - 99;  cc = 33; }
        if (plane < 8) {
            tp[plane * 1156 + rr * 34 + cc] = 0.f;
        } else {
            xs[(plane - 8) * XS_SIZE + rr * XS_STRIDE + (cc + 1)] = 0.f;
        }
    }

    // ---- per-cell softmax (x2), sigmoid restart, bias ----
    float tpv[2][8], restart[2], omr[2], bias[2];
    const float xv_in[2] = {xin.x, xin.y};
    #pragma unroll
    for (int j = 0; j < 2; j++) {
        const float4 lo = j ? wcb_lo : wca_lo;
        const float4 hi = j ? wcb_hi : wca_hi;
        float e[8], s = 0.f;
        e[0] = __expf(wt_lo.x + lo.x);  e[1] = __expf(wt_lo.y + lo.y);
        e[2] = __expf(wt_lo.z + lo.z);  e[3] = __expf(wt_lo.w + lo.w);
        e[4] = __expf(wt_hi.x + hi.x);  e[5] = __expf(wt_hi.y + hi.y);
        e[6] = __expf(wt_hi.z + hi.z);  e[7] = __expf(wt_hi.w + hi.w);
        #pragma unroll
        for (int d = 0; d < 8; d++) s += e[d];
        const float inv_s = __fdividef(1.0f, s);
        #pragma unroll
        for (int d = 0; d < 8; d++) tpv[j][d] = e[d] * inv_s;

        const float rz = wr_te + (j ? wrc.y : wrc.x);
        restart[j] = __fdividef(1.0f, 1.0f + __expf(-rz));
        omr[j] = 1.0f - restart[j];
        bias[j] = (wb_te + (j ? wbc.y : wbc.x)) * xv_in[j];
    }

    // ---- static outputs ----
    #pragma unroll
    for (int j = 0; j < 2; j++) {
        float4* t4 = reinterpret_cast<float4*>(out + OFF_T + (size_t)(bp * NUM_CELLS + cell0 + j) * 8);
        t4[0] = make_float4(tpv[j][0], tpv[j][1], tpv[j][2], tpv[j][3]);
        t4[1] = make_float4(tpv[j][4], tpv[j][5], tpv[j][6], tpv[j][7]);
    }
    *reinterpret_cast<float2*>(out + OFF_R + bp * NUM_CELLS + cell0) =
        make_float2(restart[0], restart[1]);

    // fill tp interior (disjoint from border zeroes -> one barrier below suffices)
    const int tctr = (h + 1) * 34 + (wp + 1);
    #pragma unroll
    for (int d = 0; d < 8; d++) {
        tp[d * 1156 + tctr]     = tpv[0][d];
        tp[d * 1156 + tctr + 1] = tpv[1][d];
    }
    __syncthreads();

    // DIRS d: 0:(-1,-1) 1:(-1,0) 2:(-1,1) 3:(0,-1) 4:(0,1) 5:(1,-1) 6:(1,0) 7:(1,1)
    const int DOF[8] = {-35, -34, -33, -1, 1, 33, 34, 35};
    float w_in[2][8];
    #pragma unroll
    for (int d = 0; d < 8; d++) {
        w_in[0][d] = tp[d * 1156 + tctr + DOF[d]];
        w_in[1][d] = tp[d * 1156 + tctr + 1 + DOF[d]];
    }

    // ---- iterate: pair cells share mid-row neighbors from registers ----
    float x0v = xv_in[0], x1v = xv_in[1];
    stage[cell0 * 13]      = x0v;
    stage[(cell0 + 1) * 13] = x1v;

    const int ctr = (h + 1) * XS_STRIDE + (wp + 2);   // even -> 8B aligned

    #pragma unroll
    for (int k = 0; k < KSTEP; k++) {
        float* xb = xs + (k & 1) * XS_SIZE;
        *reinterpret_cast<float2*>(&xb[ctr]) = make_float2(x0v, x1v);
        __syncthreads();

        // top row (cols wp+1..wp+4): scalar, LDS.64, scalar
        const float  tL = xb[ctr - XS_STRIDE - 1];
        const float2 tC = *reinterpret_cast<const float2*>(&xb[ctr - XS_STRIDE]);
        const float  tR = xb[ctr - XS_STRIDE + 2];
        // mid row: only outer neighbors (inner ones are x0v/x1v in regs)
        const float  mL = xb[ctr - 1];
        const float  mR = xb[ctr + 2];
        // bottom row
        const float  bL = xb[ctr + XS_STRIDE - 1];
        const float2 bC = *reinterpret_cast<const float2*>(&xb[ctr + XS_STRIDE]);
        const float  bR = xb[ctr + XS_STRIDE + 2];

        // cell0
        float a0 = tL   * w_in[0][0];
        float a1 = tC.x * w_in[0][1];
        float a2 = tC.y * w_in[0][2];
        float a3 = mL   * w_in[0][3];
        a0 = fmaf(x1v, w_in[0][4], a0);
        a1 = fmaf(bL,  w_in[0][5], a1);
        a2 = fmaf(bC.x, w_in[0][6], a2);
        a3 = fmaf(bC.y, w_in[0][7], a3);
        const float xt0 = (a0 + a1) + (a2 + a3);
        // cell1
        float c0 = tC.x * w_in[1][0];
        float c1 = tC.y * w_in[1][1];
        float c2 = tR   * w_in[1][2];
        float c3 = x0v  * w_in[1][3];
        c0 = fmaf(mR,   w_in[1][4], c0);
        c1 = fmaf(bC.x, w_in[1][5], c1);
        c2 = fmaf(bC.y, w_in[1][6], c2);
        c3 = fmaf(bR,   w_in[1][7], c3);
        const float xt1 = (c0 + c1) + (c2 + c3);

        x0v = fmaf(omr[0], xt0, fmaf(restart[0], x0v, bias[0]));
        x1v = fmaf(omr[1], xt1, fmaf(restart[1], x1v, bias[1]));
        stage[cell0 * 13 + (k + 1)]       = x0v;
        stage[(cell0 + 1) * 13 + (k + 1)] = x1v;
    }

    // final state x + Y
    *reinterpret_cast<float2*>(out + OFF_X + bp * NUM_CELLS + cell0) = make_float2(x0v, x1v);
    if (p == PP - 1)
        *reinterpret_cast<float2*>(out + OFF_Y + b * NUM_CELLS + cell0) = make_float2(x0v, x1v);

    // ---- one barrier, then fully coalesced results dump (3328 float4) ----
    __syncthreads();
    const float4* s4 = reinterpret_cast<const float4*>(stage);
    float4* o4 = reinterpret_cast<float4*>(out + OFF_RES + (size_t)bp * (NUM_CELLS * 13));
    #pragma unroll
    for (int i = 0; i < 7; i++) {
        const int idx = tid + i * 512;
        if (idx < 3328) o4[idx] = s4[idx];
    }
}

extern "C" void kernel_launch(void* const* d_in, const int* in_sizes, int n_in,
                              void* d_out, int out_size) {
    const float* X  = (const float*)d_in[0];
    const int*   TE = (const int*)d_in[1];
    const float* Wt = (const float*)d_in[2];
    const float* Wr = (const float*)d_in[3];
    const float* Wb = (const float*)d_in[4];
    float* out = (float*)d_out;
    const int smem_bytes = SMEM_FLOATS * 4;   // 100032 B
    cudaFuncSetAttribute(rwr_kernel, cudaFuncAttributeMaxDynamicSharedMemorySize, smem_bytes);
    rwr_kernel<<<BB * PP, 512, smem_bytes>>>(X, TE, Wt, Wr, Wb, out);
}

// round 7
// speedup vs baseline: 1.0509x; 1.0269x over previous
#include <cuda_runtime.h>

// Problem constants
#define PP 12
#define BB 4
#define KSTEP 12
#define TE_DEPTH 168
#define NUM_CELLS 1024   // 32*32
#define PQ 24            // P + Q

// Output layout (tuple flattened, row-major each):
//  Y       (B,1,H,W,1)       4096   @ 0
//  x       (B,P,H,W,1)      49152   @ 4096
//  trans   (B,P,H,W,8,1)   393216   @ 53248
//  restart (B,P,H,W,1)      49152   @ 446464
//  results (B,P,H,W,1,13)  638976   @ 495616
#define OFF_Y    0
#define OFF_X    4096
#define OFF_T    53248
#define OFF_R    446464
#define OFF_RES  495616

// Dynamic smem layout (floats):
//  tp    @ 0      : 8 planes of 34x34 (9248)
//  xs    @ 9248   : 2 buffers of 34x34 (2312)
//  stage @ 11560  : 1024*13 results staging (13312)
//  wte_s @ 24872  : Wt[0:168] rows (1344)
//  wr_s  @ 26216  : Wr[0:168] (168)
//  wb_s  @ 26384  : Wb[0:168] (168)
#define TP_OFF    0
#define XS_OFF    9248
#define STG_OFF   11560
#define WTE_OFF   24872
#define WR_OFF    26216
#define WB_OFF    26384
#define SMEM_FLOATS 26552   // 106208 B

__global__ __launch_bounds__(1024, 1) void rwr_kernel(
    const float* __restrict__ X,
    const int*   __restrict__ TE,
    const float* __restrict__ Wt,   // (1192, 8)
    const float* __restrict__ Wr,   // (1192, 1)
    const float* __restrict__ Wb,   // (1192, 1)
    float*       __restrict__ out)
{
    extern __shared__ __align__(16) float sm[];
    float* tp    = sm + TP_OFF;     // tp[d*1156 + r*34 + c]
    float* xs    = sm + XS_OFF;     // xs[buf*1156 + r*34 + c]
    float* stage = sm + STG_OFF;
    float* wte_s = sm + WTE_OFF;
    float* wr_s  = sm + WR_OFF;
    float* wb_s  = sm + WB_OFF;

    const int bp   = blockIdx.x;        // 0..47
    const int b    = bp / PP;
    const int p    = bp % PP;
    const int cell = threadIdx.x;       // 0..1023
    const int h    = cell >> 5;
    const int w    = cell & 31;

    // ---- issue ALL independent global loads at cycle 0 (max MLP) ----
    const float x0 = X[bp * NUM_CELLS + cell];
    const int te_day  = TE[(b * PQ + p) * 2 + 0];
    const int te_hour = TE[(b * PQ + p) * 2 + 1];
    const int cr = TE_DEPTH + cell;

    const float4* wc4 = reinterpret_cast<const float4*>(Wt + (size_t)cr * 8);
    const float4 wc_lo = wc4[0];
    const float4 wc_hi = wc4[1];
    const float wr_c = Wr[cr];
    const float wb_c = Wb[cr];

    // speculative te-block load -> smem (independent of TE value):
    //  Wt[0:168] = 336 float4; Wr[0:168] = 42 float4; Wb[0:168] = 42 float4
    if (cell < 420) {
        float4 v;
        if (cell < 336)      v = reinterpret_cast<const float4*>(Wt)[cell];
        else if (cell < 378) v = reinterpret_cast<const float4*>(Wr)[cell - 336];
        else                 v = reinterpret_cast<const float4*>(Wb)[cell - 378];
        float4* dst;
        if (cell < 336)      dst = reinterpret_cast<float4*>(wte_s) + cell;
        else if (cell < 378) dst = reinterpret_cast<float4*>(wr_s) + (cell - 336);
        else                 dst = reinterpret_cast<float4*>(wb_s) + (cell - 378);
        *dst = v;
    }

    // ---- zero ONLY borders: tp planes (8*132) + xs buffers (2*132) ----
    // (read only after BAR#2; disjoint from interior fills)
    #pragma unroll
    for (int i = cell; i < 1320; i += 1024) {
        const int plane = i / 132;       // 0..7 tp, 8..9 xs
        const int j = i % 132;
        int rr, cc;
        if      (j <  34) { rr = 0;       cc = j; }
        else if (j <  68) { rr = 33;      cc = j - 34; }
        else if (j < 100) { rr = j - 67;  cc = 0;  }
        else              { rr = j - 99;  cc = 33; }
        float* base = (plane < 8) ? (tp + plane * 1156)
                                  : (xs + (plane - 8) * 1156);
        base[rr * 34 + cc] = 0.f;
    }

    __syncthreads();   // BAR#1: te-block resident in smem

    // ---- read te row from smem (no second DRAM trip) ----
    const int te = te_day * 24 + te_hour;            // < 168
    const float4 wt_lo = reinterpret_cast<const float4*>(wte_s)[te * 2];
    const float4 wt_hi = reinterpret_cast<const float4*>(wte_s)[te * 2 + 1];
    const float wr_te = wr_s[te];
    const float wb_te = wb_s[te];

    // ---- softmax over 8 dirs (fast math; logits tiny, skip max-sub) ----
    float e[8], s = 0.f;
    e[0] = __expf(wt_lo.x + wc_lo.x);  e[1] = __expf(wt_lo.y + wc_lo.y);
    e[2] = __expf(wt_lo.z + wc_lo.z);  e[3] = __expf(wt_lo.w + wc_lo.w);
    e[4] = __expf(wt_hi.x + wc_hi.x);  e[5] = __expf(wt_hi.y + wc_hi.y);
    e[6] = __expf(wt_hi.z + wc_hi.z);  e[7] = __expf(wt_hi.w + wc_hi.w);
    #pragma unroll
    for (int d = 0; d < 8; d++) s += e[d];
    const float inv_s = __fdividef(1.0f, s);
    float tpv[8];
    #pragma unroll
    for (int d = 0; d < 8; d++) tpv[d] = e[d] * inv_s;

    const float rz = wr_te + wr_c;
    const float restart = __fdividef(1.0f, 1.0f + __expf(-rz));
    const float one_m_r = 1.0f - restart;
    const float bias = (wb_te + wb_c) * x0;

    // ---- static outputs (fire-and-forget) ----
    {
        float4* t4 = reinterpret_cast<float4*>(out + OFF_T + (size_t)(bp * NUM_CELLS + cell) * 8);
        t4[0] = make_float4(tpv[0], tpv[1], tpv[2], tpv[3]);
        t4[1] = make_float4(tpv[4], tpv[5], tpv[6], tpv[7]);
    }
    out[OFF_R + bp * NUM_CELLS + cell] = restart;

    // ---- fill tp interior + x0 into xs buf0 + stage[0] (all pre-BAR#2) ----
    const int ctr = (h + 1) * 34 + (w + 1);
    #pragma unroll
    for (int d = 0; d < 8; d++) tp[d * 1156 + ctr] = tpv[d];
    xs[ctr] = x0;                    // buf 0
    stage[cell * 13] = x0;

    __syncthreads();   // BAR#2: tp + xs buf0 ready -> gather + iter 0

    // DIRS d: 0:(-1,-1) 1:(-1,0) 2:(-1,1) 3:(0,-1) 4:(0,1) 5:(1,-1) 6:(1,0) 7:(1,1)
    const int DOF[8] = {-35, -34, -33, -1, 1, 33, 34, 35};
    float w_in[8];
    #pragma unroll
    for (int d = 0; d < 8; d++)
        w_in[d] = tp[d * 1156 + ctr + DOF[d]];

    // ---- iterate: iter 0 uses pre-stored buf0; iters 1..11 store+BAR ----
    float x = x0;
    #pragma unroll
    for (int k = 0; k < KSTEP; k++) {
        float* xb = xs + (k & 1) * 1156;
        if (k > 0) {
            xb[ctr] = x;
            __syncthreads();
        }
        float a0 = xb[ctr - 35] * w_in[0];
        float a1 = xb[ctr - 34] * w_in[1];
        float a2 = xb[ctr - 33] * w_in[2];
        float a3 = xb[ctr -  1] * w_in[3];
        a0 = fmaf(xb[ctr +  1], w_in[4], a0);
        a1 = fmaf(xb[ctr + 33], w_in[5], a1);
        a2 = fmaf(xb[ctr + 34], w_in[6], a2);
        a3 = fmaf(xb[ctr + 35], w_in[7], a3);
        const float xt = (a0 + a1) + (a2 + a3);
        x = fmaf(one_m_r, xt, fmaf(restart, x, bias));
        stage[cell * 13 + (k + 1)] = x;     // odd stride -> conflict-free
    }

    // final state x (coalesced) + Y
    out[OFF_X + bp * NUM_CELLS + cell] = x;
    if (p == PP - 1)
        out[OFF_Y + b * NUM_CELLS + cell] = x;

    // ---- one barrier, then fully coalesced results dump (3328 float4) ----
    __syncthreads();
    const float4* s4 = reinterpret_cast<const float4*>(stage);
    float4* o4 = reinterpret_cast<float4*>(out + OFF_RES + (size_t)bp * (NUM_CELLS * 13));
    #pragma unroll
    for (int i = 0; i < 4; i++) {
        const int idx = cell + i * 1024;
        if (idx < 3328) o4[idx] = s4[idx];
    }
}

extern "C" void kernel_launch(void* const* d_in, const int* in_sizes, int n_in,
                              void* d_out, int out_size) {
    const float* X  = (const float*)d_in[0];
    const int*   TE = (const int*)d_in[1];
    const float* Wt = (const float*)d_in[2];
    const float* Wr = (const float*)d_in[3];
    const float* Wb = (const float*)d_in[4];
    float* out = (float*)d_out;
    const int smem_bytes = SMEM_FLOATS * 4;   // 106208 B
    cudaFuncSetAttribute(rwr_kernel, cudaFuncAttributeMaxDynamicSharedMemorySize, smem_bytes);
    rwr_kernel<<<BB * PP, 1024, smem_bytes>>>(X, TE, Wt, Wr, Wb, out);
}